// round 7
// baseline (speedup 1.0000x reference)
#include <cuda_runtime.h>

#define RES     96
#define EPSF    1e-5f
#define CAP     (RES * RES)      // 9216 compacted-source capacity
#define NBANDS  12               // 8-row bands
#define MAXT    36               // tiles (actual 34)
#define GRID    148

// Global scratch (static — no cudaMalloc).
__device__ float        g_part[MAXT * 4 * 256];  // 4 K-quarters x 256 targets per tile
__device__ unsigned int g_tick[MAXT];            // monotone arrival tickets (replay-safe)

// ==============================================================================
// Single kernel, 148 blocks x 1024 threads (1 block/SM, single wave).
// Block idx -> (tile t = idx/4, K-quarter h = idx%4); 34 tiles x 4 = 136 working.
// Tile = 8 i-rows x 32 j (adaptive window). Per source per lane: 8 terms,
// 8 RCP, ~36 issues -> MUFU saturates at IPC ~0.56.
// 4th-arriving block per tile combines the 4 quarter-partials in fixed order.
// ==============================================================================
__global__ void __launch_bounds__(1024, 1) fused_kernel(
    const float* __restrict__ b, float* __restrict__ out)
{
    extern __shared__ float4 ent[];              // CAP * 16 B dynamic
    __shared__ int   cnts[RES], offs[RES], sK;
    __shared__ int   tnw[NBANDS], tJ0[NBANDS], toff[NBANDS], ttab[MAXT], sWT;
    __shared__ float red[32 * 256];              // 32 warps x 256 targets
    __shared__ int   sflag;

    const int tid  = threadIdx.x;
    const int wid  = tid >> 5;
    const int lane = tid & 31;

    // ---- tile geometry (input-independent): band p rows 8p..8p+7 ----
    if (tid < NBANDS) {
        const int r0 = tid * 8;
        int dmin = 1000;
        #pragma unroll
        for (int r = 0; r < 8; r++) { int d = r0 + r - 48; if (d < 0) d = -d; if (d < dmin) dmin = d; }
        const int v = 2208 - dmin * dmin;
        int nw = 0, J0 = 0;
        if (v >= 0) {
            int wI = (int)sqrtf((float)v);
            while ((wI + 1) * (wI + 1) <= v) wI++;     // exact isqrt
            while (wI * wI > v) wI--;
            J0 = 47 - wI; if (J0 < 0) J0 = 0;
            nw = (2 * wI + 2 + 31) >> 5;               // <= 3
        }
        tnw[tid] = nw; tJ0[tid] = J0;
    }
    __syncthreads();
    if (tid == 0) {
        int s = 0;
        #pragma unroll 1
        for (int p = 0; p < NBANDS; p++) { toff[p] = s; s += tnw[p]; }
        sWT = s;                                       // 34
    }
    __syncthreads();
    if (tid < NBANDS)
        for (int g = 0; g < tnw[tid]; g++)
            ttab[toff[tid] + g] = tid | (g << 8) | (tJ0[tid] << 16);
    __syncthreads();

    const int WT = sWT;
    if ((int)blockIdx.x >= 4 * WT) return;             // idle blocks exit

    // ---- compaction: positive boundary -> (bi, bj, w, 0), row-major order ----
    {
        const int r0 = wid * 3;
        #pragma unroll
        for (int rr = 0; rr < 3; rr++) {
            const int row = r0 + rr;
            int c = 0;
            #pragma unroll
            for (int s = 0; s < 3; s++) {
                float v = b[row * RES + s * 32 + lane];
                c += __popc(__ballot_sync(0xffffffffu, v > 0.0f));
            }
            if (lane == 0) cnts[row] = c;
        }
    }
    __syncthreads();
    if (wid == 0) {                                    // exclusive prefix of 96 counts
        int a0 = cnts[lane], a1 = cnts[lane + 32], a2 = cnts[lane + 64];
        int s0 = a0, s1 = a1, s2 = a2;
        #pragma unroll
        for (int d = 1; d < 32; d <<= 1) {
            int t0 = __shfl_up_sync(0xffffffffu, s0, d); if (lane >= d) s0 += t0;
            int t1 = __shfl_up_sync(0xffffffffu, s1, d); if (lane >= d) s1 += t1;
            int t2 = __shfl_up_sync(0xffffffffu, s2, d); if (lane >= d) s2 += t2;
        }
        s1 += __shfl_sync(0xffffffffu, s0, 31);
        s2 += __shfl_sync(0xffffffffu, s1, 31);
        offs[lane]      = s0 - a0;
        offs[lane + 32] = s1 - a1;
        offs[lane + 64] = s2 - a2;
        if (lane == 31) sK = s2;
    }
    __syncthreads();
    {
        const int r0 = wid * 3;
        #pragma unroll
        for (int rr = 0; rr < 3; rr++) {
            const int row = r0 + rr;
            int p = offs[row];
            #pragma unroll
            for (int s = 0; s < 3; s++) {
                const int col = s * 32 + lane;
                float v = b[row * RES + col];
                unsigned m = __ballot_sync(0xffffffffu, v > 0.0f);
                if (v > 0.0f) {
                    int pos = p + __popc(m & ((1u << lane) - 1u));
                    ent[pos] = make_float4((float)row, (float)col, v, 0.0f);
                }
                p += __popc(m);
            }
        }
    }
    __syncthreads();

    // ---- rim passthrough for uncovered columns (blocks 0..11 own their band) ----
    if (blockIdx.x < NBANDS && tid < RES) {
        const int band = blockIdx.x, j = tid;
        const int nw = tnw[band], J0p = tJ0[band];
        const bool covered = (nw > 0) && (j >= J0p) && (j < J0p + 32 * nw);
        if (!covered) {
            const int r0 = band * 8;
            #pragma unroll
            for (int r = 0; r < 8; r++)
                out[(r0 + r) * RES + j] = b[(r0 + r) * RES + j];
        }
    }

    // ---- per-block work: tile t, K-quarter h ----
    const int t    = blockIdx.x >> 2;
    const int h    = blockIdx.x & 3;
    const int info = ttab[t];
    const int band = info & 255;
    const int g    = (info >> 8) & 255;
    const int J0   = info >> 16;
    const int i0   = band * 8;

    const int   j   = J0 + 32 * g + lane;              // may be >= 96 (discarded later)
    const float fj  = (float)j;
    const float fi0 = (float)i0;

    // per-lane constants: z per row (reference-faithful f32 sqrt), fp64 combine for k_r
    float zs[8];
    {
        const float djc = fj - 48.0f;
        const float dj2 = djc * djc;                   // exact integer-valued
        #pragma unroll
        for (int r = 0; r < 8; r++) {
            float dic = (float)(i0 + r) - 48.0f;
            zs[r] = 48.0f - sqrtf(fmaf(dic, dic, dj2)) + EPSF;
        }
    }
    const float c00 = fmaf(zs[0], zs[0], EPSF * EPSF);
    float kk[8];
    #pragma unroll
    for (int r = 1; r < 8; r++)
        kk[r] = (float)((double)(r * r)
                        + ((double)zs[r] * (double)zs[r]
                           - (double)zs[0] * (double)zs[0]));

    // any interior target in this warp's 8x32 patch? (block-uniform)
    bool any = false;
    {
        const int djq = (j - 48) * (j - 48);
        #pragma unroll
        for (int r = 0; r < 8; r++) {
            const int di = i0 + r - 48;
            if (di * di + djq < 2209) any = true;
        }
    }
    const bool work = __any_sync(0xffffffffu, any);

    const int K  = sK;
    const int sa = (K * h) >> 2;
    const int sb = (K * (h + 1)) >> 2;

    float a0 = 0.f, a1 = 0.f, a2 = 0.f, a3 = 0.f,
          a4 = 0.f, a5 = 0.f, a6 = 0.f, a7 = 0.f;

    if (work) {
        #pragma unroll 2
        for (int s = sa + wid; s < sb; s += 32) {
            const float4 e  = ent[s];                  // broadcast LDS.128
            const float dj  = fj  - e.y;
            const float di0 = fi0 - e.x;
            const float u0   = fmaf(dj,  dj,  c00);
            const float den0 = fmaf(di0, di0, u0);
            const float den1 = den0 + fmaf(di0,  2.0f, kk[1]);
            const float den2 = den0 + fmaf(di0,  4.0f, kk[2]);
            const float den3 = den0 + fmaf(di0,  6.0f, kk[3]);
            const float den4 = den0 + fmaf(di0,  8.0f, kk[4]);
            const float den5 = den0 + fmaf(di0, 10.0f, kk[5]);
            const float den6 = den0 + fmaf(di0, 12.0f, kk[6]);
            const float den7 = den0 + fmaf(di0, 14.0f, kk[7]);
            float v0, v1, v2, v3, v4, v5, v6, v7;
            asm("rcp.approx.ftz.f32 %0, %1;" : "=f"(v0) : "f"(den0));
            asm("rcp.approx.ftz.f32 %0, %1;" : "=f"(v1) : "f"(den1));
            asm("rcp.approx.ftz.f32 %0, %1;" : "=f"(v2) : "f"(den2));
            asm("rcp.approx.ftz.f32 %0, %1;" : "=f"(v3) : "f"(den3));
            asm("rcp.approx.ftz.f32 %0, %1;" : "=f"(v4) : "f"(den4));
            asm("rcp.approx.ftz.f32 %0, %1;" : "=f"(v5) : "f"(den5));
            asm("rcp.approx.ftz.f32 %0, %1;" : "=f"(v6) : "f"(den6));
            asm("rcp.approx.ftz.f32 %0, %1;" : "=f"(v7) : "f"(den7));
            a0 = fmaf(e.z, v0, a0);
            a1 = fmaf(e.z, v1, a1);
            a2 = fmaf(e.z, v2, a2);
            a3 = fmaf(e.z, v3, a3);
            a4 = fmaf(e.z, v4, a4);
            a5 = fmaf(e.z, v5, a5);
            a6 = fmaf(e.z, v6, a6);
            a7 = fmaf(e.z, v7, a7);
        }
    }

    // ---- intra-block reduction: 32 warps -> 256 partials ----
    red[wid * 256 +   0 + lane] = a0;
    red[wid * 256 +  32 + lane] = a1;
    red[wid * 256 +  64 + lane] = a2;
    red[wid * 256 +  96 + lane] = a3;
    red[wid * 256 + 128 + lane] = a4;
    red[wid * 256 + 160 + lane] = a5;
    red[wid * 256 + 192 + lane] = a6;
    red[wid * 256 + 224 + lane] = a7;
    __syncthreads();

    if (tid < 256) {
        float part = 0.0f;
        #pragma unroll 8
        for (int w = 0; w < 32; w++) part += red[w * 256 + tid];
        g_part[(t * 4 + h) * 256 + tid] = part;
    }
    __threadfence();                                   // publish partials (gpu scope)
    __syncthreads();
    if (tid == 0) {
        unsigned old = atomicAdd(&g_tick[t], 1u);
        sflag = ((old & 3u) == 3u);                    // 4th arrival this launch
        __threadfence();                               // acquire-side fence
    }
    __syncthreads();

    // ---- 4th-arriving block combines the 4 quarters (fixed order) & writes ----
    if (sflag && tid < 256) {
        float s = 0.0f;
        #pragma unroll
        for (int h2 = 0; h2 < 4; h2++)
            s += __ldcg(&g_part[(t * 4 + h2) * 256 + tid]);
        const int row = i0 + (tid >> 5);
        const int col = J0 + 32 * g + (tid & 31);
        if (col < RES) {
            const int di = row - 48, dj = col - 48;
            const float bv = b[row * RES + col];
            out[row * RES + col] = (di * di + dj * dj >= 2209) ? bv : s;
        }
    }
}

// ------------------------------------------------------------------------------
extern "C" void kernel_launch(void* const* d_in, const int* in_sizes, int n_in,
                              void* d_out, int out_size) {
    (void)in_sizes; (void)n_in; (void)out_size;
    const float* b   = (const float*)d_in[0];
    float*       out = (float*)d_out;

    const int smem_bytes = CAP * (int)sizeof(float4);  // 147456 dynamic
    cudaFuncSetAttribute(fused_kernel,
                         cudaFuncAttributeMaxDynamicSharedMemorySize, smem_bytes);

    fused_kernel<<<GRID, 1024, smem_bytes>>>(b, out);
}

// round 8
// speedup vs baseline: 1.4467x; 1.4467x over previous
#include <cuda_runtime.h>
#include <cuda_fp16.h>

#define RES     96
#define CENTERF 48.0f
#define EPSF    1e-5f
#define CAP     (RES * RES)          // 9216 entries — overflow impossible
#define NWARPS  32                   // 1024 threads/block
#define RIM2    2209.0f              // 47^2, exact in fp32

// ---------------------------------------------------------------------------
// Single kernel.  Grid: 144 = 48 i-pairs x 3 adaptive j-windows.
// Block: 1024 threads (32 warps splitting the compacted source list).
//
// Phase 1: ballot compaction of positive boundary values into SMEM as
//          uint4 records of duplicated half2s: (h2(-bi,-bi), h2(bj,bj),
//          h2(w,w), 0).  Deterministic (row,col) order.
// Phase 2: 2 i-rows per lane packed as the two f16 lanes of half2 math:
//            dj2 = fj2 - bj2            (exact ints in f16)
//            di2 = fi01 + nbi2          (exact)
//            uv  = hfma2(dj2,dj2,c2)    (c2 = {z0^2+eps^2, z1^2+eps^2})
//            den = hfma2(di2,di2,uv)
//            inv = h2rcp(den)           <- ONE MUFU for TWO terms
//            acc2 += w2 * inv           (f16x2 accum, flushed to f32 every
//                                        4 iterations for precision)
//          The 2*eps*sqrt(d2) cross term of the reference is dropped
//          (relative contribution <= eps/z <= 1e-5 for interior targets).
// Phase 3: f32 cross-warp reduction, exact integer rim select, store.
// ---------------------------------------------------------------------------
__global__ void __launch_bounds__(1024, 1) fused_kernel(
    const float* __restrict__ b, float* __restrict__ out)
{
    extern __shared__ uint4 ent[];           // CAP entries, 147456 B dynamic
    __shared__ int   cnts[RES];
    __shared__ int   offs[RES];
    __shared__ int   sK;
    __shared__ float red[NWARPS * 64];

    const int tid  = threadIdx.x;
    const int wid  = tid >> 5;
    const int lane = tid & 31;

    // ---------------- Phase 1: compaction ----------------
    {
        const int r0 = wid * 3;
        #pragma unroll
        for (int rr = 0; rr < 3; rr++) {
            const int row = r0 + rr;
            int c = 0;
            #pragma unroll
            for (int s = 0; s < 3; s++) {
                float v = b[row * RES + s * 32 + lane];
                c += __popc(__ballot_sync(0xffffffffu, v > 0.0f));
            }
            if (lane == 0) cnts[row] = c;
        }
    }
    __syncthreads();

    if (wid == 0) {  // exclusive prefix over 96 row counts
        int a0 = cnts[lane], a1 = cnts[lane + 32], a2 = cnts[lane + 64];
        int s0 = a0, s1 = a1, s2 = a2;
        #pragma unroll
        for (int d = 1; d < 32; d <<= 1) {
            int t0 = __shfl_up_sync(0xffffffffu, s0, d); if (lane >= d) s0 += t0;
            int t1 = __shfl_up_sync(0xffffffffu, s1, d); if (lane >= d) s1 += t1;
            int t2 = __shfl_up_sync(0xffffffffu, s2, d); if (lane >= d) s2 += t2;
        }
        s1 += __shfl_sync(0xffffffffu, s0, 31);
        s2 += __shfl_sync(0xffffffffu, s1, 31);
        offs[lane]      = s0 - a0;
        offs[lane + 32] = s1 - a1;
        offs[lane + 64] = s2 - a2;
        if (lane == 31) sK = s2;
    }
    __syncthreads();

    {
        const int r0 = wid * 3;
        #pragma unroll
        for (int rr = 0; rr < 3; rr++) {
            const int row = r0 + rr;
            int p = offs[row];
            #pragma unroll
            for (int s = 0; s < 3; s++) {
                const int col = s * 32 + lane;
                float v = b[row * RES + col];
                unsigned m = __ballot_sync(0xffffffffu, v > 0.0f);
                if (v > 0.0f) {
                    int pos = p + __popc(m & ((1u << lane) - 1u));
                    __half2 nb2 = __half2half2(__float2half_rn(-(float)row));
                    __half2 bj2 = __half2half2(__float2half_rn((float)col));
                    __half2 w2  = __half2half2(__float2half_rn(v));
                    uint4 rec;
                    rec.x = *reinterpret_cast<unsigned int*>(&nb2);
                    rec.y = *reinterpret_cast<unsigned int*>(&bj2);
                    rec.z = *reinterpret_cast<unsigned int*>(&w2);
                    rec.w = 0u;
                    ent[pos] = rec;
                }
                p += __popc(m);
            }
        }
    }
    __syncthreads();

    // ---------------- window placement (R3-proven) ----------------
    const int pp  = blockIdx.x / 3;
    const int g   = blockIdx.x % 3;
    const int i0  = 2 * pp;

    const int a0i = abs(i0 - 48);
    const int a1i = abs(i0 + 1 - 48);
    const int dmin = a0i < a1i ? a0i : a1i;
    int s_ = 2208 - dmin * dmin; if (s_ < 0) s_ = 0;
    const int wmax = (int)sqrtf((float)s_) + 1;   // over-estimate: safe
    int J0 = 48 - wmax; if (J0 < 0) J0 = 0;

    const int j   = J0 + 32 * g + lane;           // may exceed 95 (guarded)
    const float fi0 = (float)i0;
    const float fj  = (float)j;

    const float dic0 = fi0 - CENTERF;
    const float dic1 = dic0 + 1.0f;
    const float djc  = fj - CENTERF;
    const float r2_0 = dic0 * dic0 + djc * djc;   // exact integer-valued
    const float r2_1 = dic1 * dic1 + djc * djc;
    const float z0 = CENTERF - sqrtf(r2_0) + EPSF;
    const float z1 = CENTERF - sqrtf(r2_1) + EPSF;
    const float c00 = fmaf(z0, z0, EPSF * EPSF);
    const float c01 = fmaf(z1, z1, EPSF * EPSF);

    const __half2 c2    = __floats2half2_rn(c00, c01);
    const __half2 fi012 = __floats2half2_rn(fi0, fi0 + 1.0f);
    const __half2 fj2   = __half2half2(__float2half_rn(fj));
    const __half2 zero2 = __floats2half2_rn(0.0f, 0.0f);

    const bool allrim = __all_sync(0xffffffffu,
                                   (r2_0 >= RIM2) && (r2_1 >= RIM2));
    const int K = sK;
    float f0 = 0.0f, f1 = 0.0f;

    // ---------------- Phase 2: potential (f16x2 core) ----------------
    if (!allrim) {
        __half2 acc2 = zero2;
        int idx = wid;
        const int nfull = (K > wid) ? (K - wid + 31) / 32 : 0;  // this warp's iters
        const int nb4 = nfull >> 2;

        for (int b4 = 0; b4 < nb4; b4++) {
            #pragma unroll
            for (int u = 0; u < 4; u++) {
                uint4 e = ent[idx];                            // broadcast LDS.128
                __half2 nbi2 = *reinterpret_cast<__half2*>(&e.x);
                __half2 bj2  = *reinterpret_cast<__half2*>(&e.y);
                __half2 w2   = *reinterpret_cast<__half2*>(&e.z);
                __half2 dj2  = __hsub2(fj2, bj2);
                __half2 di2  = __hadd2(fi012, nbi2);
                __half2 uv   = __hfma2(dj2, dj2, c2);
                __half2 den  = __hfma2(di2, di2, uv);
                __half2 inv  = h2rcp(den);
                acc2 = __hfma2(w2, inv, acc2);
                idx += 32;
            }
            // flush f16 accumulator to f32 (bounds f16 accumulation error)
            f0 += __low2float(acc2);
            f1 += __high2float(acc2);
            acc2 = zero2;
        }
        for (int r = nb4 * 4; r < nfull; r++) {
            uint4 e = ent[idx];
            __half2 nbi2 = *reinterpret_cast<__half2*>(&e.x);
            __half2 bj2  = *reinterpret_cast<__half2*>(&e.y);
            __half2 w2   = *reinterpret_cast<__half2*>(&e.z);
            __half2 dj2  = __hsub2(fj2, bj2);
            __half2 di2  = __hadd2(fi012, nbi2);
            __half2 uv   = __hfma2(dj2, dj2, c2);
            __half2 den  = __hfma2(di2, di2, uv);
            __half2 inv  = h2rcp(den);
            acc2 = __hfma2(w2, inv, acc2);
            idx += 32;
        }
        f0 += __low2float(acc2);
        f1 += __high2float(acc2);
    }

    red[wid * 64 + lane]      = f0;
    red[wid * 64 + 32 + lane] = f1;
    __syncthreads();

    // ---------------- Phase 3: reduce + store ----------------
    if (tid < 64) {
        const int k = tid >> 5;                   // which of the two i-rows
        const int l = tid & 31;
        float s = 0.0f;
        #pragma unroll
        for (int w = 0; w < NWARPS; w++) s += red[w * 64 + k * 32 + l];

        const int jj = J0 + 32 * g + l;
        if (jj < RES) {
            const int ii  = i0 + k;
            const int di  = ii - 48, dj = jj - 48;
            const float bv = b[ii * RES + jj];
            out[ii * RES + jj] = (di * di + dj * dj >= 2209) ? bv : s;
        }
    }

    // Rim passthrough for uncovered columns j < J0 (provably rim).
    if (g == 0 && tid < RES) {
        if (tid < J0) {
            out[i0 * RES + tid]       = b[i0 * RES + tid];
            out[(i0 + 1) * RES + tid] = b[(i0 + 1) * RES + tid];
        }
    }
}

// ---------------------------------------------------------------------------
extern "C" void kernel_launch(void* const* d_in, const int* in_sizes, int n_in,
                              void* d_out, int out_size) {
    (void)in_sizes; (void)n_in; (void)out_size;
    const float* b   = (const float*)d_in[0];
    float*       out = (float*)d_out;

    const int smem_bytes = CAP * (int)sizeof(uint4);  // 147456
    cudaFuncSetAttribute(fused_kernel,
                         cudaFuncAttributeMaxDynamicSharedMemorySize, smem_bytes);

    fused_kernel<<<144, 1024, smem_bytes>>>(b, out);
}

// round 9
// speedup vs baseline: 1.4516x; 1.0034x over previous
#include <cuda_runtime.h>
#include <cuda_fp16.h>

#define RES     96
#define CENTERF 48.0f
#define EPSF    1e-5f
#define KPMAX   (RES * RES / 2)      // 4608 packed records max
#define NWARPS  32
#define RIM2    2209.0f              // 47^2

// ---------------------------------------------------------------------------
// Single kernel.  Grid: 144 = 48 i-pairs x 3 adaptive 32-wide j-windows.
// Block: 1024 threads = 32 warps splitting the packed source list.
//
// Source-pair packing: record k = sources (2k, 2k+1) of the compacted list,
// stored as uint4 { h2(-bi0,-bi1), h2(bj0,bj1), h2(w0,w1), 0 }.
// Per record per lane -> 4 terms (2 sources x 2 target rows), 12 issues:
//   dj2  = fj2 - bj2          di0 = fi0_2 + nbi2       di1 = fi1_2 + nbi2
//   s0   = hfma2(dj2,dj2,c0)  s1  = hfma2(dj2,dj2,c1)  (2 roundings per den)
//   den0 = hfma2(di0,di0,s0)  den1 = hfma2(di1,di1,s1)
//   acc0 += w2 * h2rcp(den0)  acc1 += w2 * h2rcp(den1)
// f16 accumulators flushed to f32 every 4 records.  The 2*eps*sqrt(d2) cross
// term of the reference is dropped (rel contribution <= eps/z <= 1e-5).
// ---------------------------------------------------------------------------
__global__ void __launch_bounds__(1024, 1) fused_kernel(
    const float* __restrict__ b, float* __restrict__ out)
{
    extern __shared__ uint4 ent[];           // KPMAX records, 73728 B dynamic
    __shared__ int   cnts[RES];
    __shared__ int   offs[RES];
    __shared__ int   sK;
    __shared__ float red[NWARPS * 64];

    const int tid  = threadIdx.x;
    const int wid  = tid >> 5;
    const int lane = tid & 31;

    // ---------------- Phase 0: zero the packed array (tail-safety) ----------
    for (int t = tid; t < KPMAX; t += 1024)
        ent[t] = make_uint4(0u, 0u, 0u, 0u);

    // ---------------- Phase 1: compaction ----------------
    {
        const int r0 = wid * 3;
        #pragma unroll
        for (int rr = 0; rr < 3; rr++) {
            const int row = r0 + rr;
            int c = 0;
            #pragma unroll
            for (int s = 0; s < 3; s++) {
                float v = b[row * RES + s * 32 + lane];
                c += __popc(__ballot_sync(0xffffffffu, v > 0.0f));
            }
            if (lane == 0) cnts[row] = c;
        }
    }
    __syncthreads();

    if (wid == 0) {  // exclusive prefix over 96 row counts
        int a0 = cnts[lane], a1 = cnts[lane + 32], a2 = cnts[lane + 64];
        int s0 = a0, s1 = a1, s2 = a2;
        #pragma unroll
        for (int d = 1; d < 32; d <<= 1) {
            int t0 = __shfl_up_sync(0xffffffffu, s0, d); if (lane >= d) s0 += t0;
            int t1 = __shfl_up_sync(0xffffffffu, s1, d); if (lane >= d) s1 += t1;
            int t2 = __shfl_up_sync(0xffffffffu, s2, d); if (lane >= d) s2 += t2;
        }
        s1 += __shfl_sync(0xffffffffu, s0, 31);
        s2 += __shfl_sync(0xffffffffu, s1, 31);
        offs[lane]      = s0 - a0;
        offs[lane + 32] = s1 - a1;
        offs[lane + 64] = s2 - a2;
        if (lane == 31) sK = s2;
    }
    __syncthreads();

    {   // scatter: element pos -> record pos>>1, half-lane pos&1
        const int r0 = wid * 3;
        #pragma unroll
        for (int rr = 0; rr < 3; rr++) {
            const int row = r0 + rr;
            int p = offs[row];
            #pragma unroll
            for (int s = 0; s < 3; s++) {
                const int col = s * 32 + lane;
                float v = b[row * RES + col];
                unsigned m = __ballot_sync(0xffffffffu, v > 0.0f);
                if (v > 0.0f) {
                    int pos = p + __popc(m & ((1u << lane) - 1u));
                    __half* hp = reinterpret_cast<__half*>(&ent[pos >> 1]);
                    const int o = pos & 1;
                    hp[0 + o] = __float2half_rn(-(float)row);
                    hp[2 + o] = __float2half_rn((float)col);
                    hp[4 + o] = __float2half_rn(v);
                }
                p += __popc(m);
            }
        }
    }
    __syncthreads();

    // ---------------- window placement (R3-proven) ----------------
    const int pp  = blockIdx.x / 3;
    const int g   = blockIdx.x % 3;
    const int i0  = 2 * pp;

    const int a0i = abs(i0 - 48);
    const int a1i = abs(i0 + 1 - 48);
    const int dmin = a0i < a1i ? a0i : a1i;
    int s_ = 2208 - dmin * dmin; if (s_ < 0) s_ = 0;
    const int wmax = (int)sqrtf((float)s_) + 1;   // over-estimate: safe
    int J0 = 48 - wmax; if (J0 < 0) J0 = 0;

    const int j   = J0 + 32 * g + lane;           // may exceed 95 (guarded)
    const float fi0 = (float)i0;
    const float fj  = (float)j;

    const float dic0 = fi0 - CENTERF;
    const float dic1 = dic0 + 1.0f;
    const float djc  = fj - CENTERF;
    const float r2_0 = dic0 * dic0 + djc * djc;   // exact integer-valued
    const float r2_1 = dic1 * dic1 + djc * djc;
    const float z0 = CENTERF - sqrtf(r2_0) + EPSF;
    const float z1 = CENTERF - sqrtf(r2_1) + EPSF;
    const float c00 = fmaf(z0, z0, EPSF * EPSF);
    const float c01 = fmaf(z1, z1, EPSF * EPSF);

    const __half2 c0_2  = __half2half2(__float2half_rn(c00));
    const __half2 c1_2  = __half2half2(__float2half_rn(c01));
    const __half2 fi0_2 = __half2half2(__float2half_rn(fi0));
    const __half2 fi1_2 = __half2half2(__float2half_rn(fi0 + 1.0f));
    const __half2 fj2   = __half2half2(__float2half_rn(fj));
    const __half2 zero2 = __floats2half2_rn(0.0f, 0.0f);

    const bool allrim = __all_sync(0xffffffffu,
                                   (r2_0 >= RIM2) && (r2_1 >= RIM2));
    const int Kp = (sK + 1) >> 1;                 // packed record count
    float f0 = 0.0f, f1 = 0.0f;

    // ---------------- Phase 2: potential (2-source x 2-row f16 core) --------
    if (!allrim) {
        __half2 acc0 = zero2, acc1 = zero2;
        const int nfull = (Kp > wid) ? (Kp - wid + 31) / 32 : 0;
        const int nb4 = nfull >> 2;
        const uint4* pe = ent + wid;

        for (int b4 = 0; b4 < nb4; b4++) {
            #pragma unroll
            for (int u = 0; u < 4; u++) {
                uint4 e = pe[u * 32];                     // LDS.128 + imm offset
                __half2 nbi2 = *reinterpret_cast<__half2*>(&e.x);
                __half2 bj2  = *reinterpret_cast<__half2*>(&e.y);
                __half2 w2   = *reinterpret_cast<__half2*>(&e.z);
                __half2 dj2  = __hsub2(fj2, bj2);
                __half2 di0  = __hadd2(fi0_2, nbi2);
                __half2 di1  = __hadd2(fi1_2, nbi2);
                __half2 s0   = __hfma2(dj2, dj2, c0_2);
                __half2 s1   = __hfma2(dj2, dj2, c1_2);
                __half2 den0 = __hfma2(di0, di0, s0);
                __half2 den1 = __hfma2(di1, di1, s1);
                __half2 inv0 = h2rcp(den0);
                __half2 inv1 = h2rcp(den1);
                acc0 = __hfma2(w2, inv0, acc0);
                acc1 = __hfma2(w2, inv1, acc1);
            }
            pe += 128;
            // flush f16 accumulators to f32 (bounds accumulation error)
            f0 += __low2float(acc0) + __high2float(acc0);
            f1 += __low2float(acc1) + __high2float(acc1);
            acc0 = zero2; acc1 = zero2;
        }
        for (int r = nb4 * 4; r < nfull; r++) {
            uint4 e = *pe; pe += 32;
            __half2 nbi2 = *reinterpret_cast<__half2*>(&e.x);
            __half2 bj2  = *reinterpret_cast<__half2*>(&e.y);
            __half2 w2   = *reinterpret_cast<__half2*>(&e.z);
            __half2 dj2  = __hsub2(fj2, bj2);
            __half2 di0  = __hadd2(fi0_2, nbi2);
            __half2 di1  = __hadd2(fi1_2, nbi2);
            __half2 s0   = __hfma2(dj2, dj2, c0_2);
            __half2 s1   = __hfma2(dj2, dj2, c1_2);
            __half2 den0 = __hfma2(di0, di0, s0);
            __half2 den1 = __hfma2(di1, di1, s1);
            __half2 inv0 = h2rcp(den0);
            __half2 inv1 = h2rcp(den1);
            acc0 = __hfma2(w2, inv0, acc0);
            acc1 = __hfma2(w2, inv1, acc1);
        }
        f0 += __low2float(acc0) + __high2float(acc0);
        f1 += __low2float(acc1) + __high2float(acc1);
    }

    red[wid * 64 + lane]      = f0;
    red[wid * 64 + 32 + lane] = f1;
    __syncthreads();

    // ---------------- Phase 3: reduce + store ----------------
    if (tid < 64) {
        const int k = tid >> 5;                   // which of the two i-rows
        const int l = tid & 31;
        float s = 0.0f;
        #pragma unroll
        for (int w = 0; w < NWARPS; w++) s += red[w * 64 + k * 32 + l];

        const int jj = J0 + 32 * g + l;
        if (jj < RES) {
            const int ii  = i0 + k;
            const int di  = ii - 48, dj = jj - 48;
            const float bv = b[ii * RES + jj];
            out[ii * RES + jj] = (di * di + dj * dj >= 2209) ? bv : s;
        }
    }

    // Rim passthrough for uncovered columns j < J0 (provably rim).
    if (g == 0 && tid < RES) {
        if (tid < J0) {
            out[i0 * RES + tid]       = b[i0 * RES + tid];
            out[(i0 + 1) * RES + tid] = b[(i0 + 1) * RES + tid];
        }
    }
}

// ---------------------------------------------------------------------------
extern "C" void kernel_launch(void* const* d_in, const int* in_sizes, int n_in,
                              void* d_out, int out_size) {
    (void)in_sizes; (void)n_in; (void)out_size;
    const float* b   = (const float*)d_in[0];
    float*       out = (float*)d_out;

    const int smem_bytes = KPMAX * (int)sizeof(uint4);  // 73728
    cudaFuncSetAttribute(fused_kernel,
                         cudaFuncAttributeMaxDynamicSharedMemorySize, smem_bytes);

    fused_kernel<<<144, 1024, smem_bytes>>>(b, out);
}

// round 10
// speedup vs baseline: 1.5892x; 1.0948x over previous
#include <cuda_runtime.h>

#define RES     96
#define CENTERF 48.0f
#define EPSF    1e-5f
#define KMAX    (RES * RES)          // 9216 — but positives <= 9216; arrays sized 4608
#define NSRC    4608                 // max positive sources observed bound (K <= 9216 but
                                     // gaussian -> ~50%; guarded by hard cap below)
#define NWARPS  32
#define RIM2    2209.0f

// NOTE: K can theoretically reach 9216; size arrays for the full 9216 to be safe.
#define CAPS    (RES * RES)          // per-source entA capacity
#define CAPP    ((CAPS + 1) / 2)     // source-pair capacity (entW)

// ---- f32x2 helpers ----------------------------------------------------------
__device__ __forceinline__ unsigned long long pk2(float a, float b) {
    unsigned long long r;
    asm("mov.b64 %0, {%1, %2};" : "=l"(r) : "f"(a), "f"(b));
    return r;
}
__device__ __forceinline__ void unpk2(unsigned long long v, float& a, float& b) {
    asm("mov.b64 {%0, %1}, %2;" : "=f"(a), "=f"(b) : "l"(v));
}
#define ADD2(d, a, b) asm("add.rn.f32x2 %0, %1, %2;" : "=l"(d) : "l"(a), "l"(b))
#define MUL2(d, a, b) asm("mul.rn.f32x2 %0, %1, %2;" : "=l"(d) : "l"(a), "l"(b))
#define FMA2(d, a, b, c) \
    asm("fma.rn.f32x2 %0, %1, %2, %3;" : "=l"(d) : "l"(a), "l"(b), "l"(c))

// ---------------------------------------------------------------------------
// Single kernel.  Grid: 144 = 48 i-pairs x 3 adaptive 32-wide j-windows.
// Block: 1024 threads = 32 warps splitting the source-pair list.
//
// SMEM layout (dynamic):
//   entA[s]  : float4 (-bi, -bi, -bj, -bj)      (per source, packed-ready)
//   entW[p]  : float4 ( w0,  w0,  w1,  w1)      (per source-pair)
// Inner loop, per source pair (rows i0,i1 in the f32x2 lanes => 4 terms):
//   di = fi01 + (-bi,-bi)      dj = fj2 + (-bj,-bj)        (exact ints)
//   u  = fma2(dj,dj,c01)       a/b = fma2(di,di,u)         (dens, 2 roundings)
//   P  = a*b                   num = w0*b + w1*a
//   acc += num * rcp(P)        <- ONE scalar RCP per f32x2 lane: 2 MUFU / 4 terms
// The 2*eps*sqrt(d2) cross term of the reference is dropped
// (relative contribution <= eps/z <= 1e-5 for interior targets).
// ---------------------------------------------------------------------------
__global__ void __launch_bounds__(1024, 1) fused_kernel(
    const float* __restrict__ b, float* __restrict__ out)
{
    extern __shared__ float4 sm[];
    float4* entA = sm;                    // CAPS  float4
    float4* entW = sm + CAPS;             // CAPP  float4
    __shared__ int   cnts[RES];
    __shared__ int   offs[RES];
    __shared__ int   sK;
    __shared__ float red[NWARPS * 64];

    const int tid  = threadIdx.x;
    const int wid  = tid >> 5;
    const int lane = tid & 31;

    // ---------------- Phase 0: zero packed arrays (tail/pad safety) ---------
    for (int t = tid; t < CAPS + CAPP; t += 1024)
        sm[t] = make_float4(0.f, 0.f, 0.f, 0.f);

    // ---------------- Phase 1: compaction ----------------
    {
        const int r0 = wid * 3;
        #pragma unroll
        for (int rr = 0; rr < 3; rr++) {
            const int row = r0 + rr;
            int c = 0;
            #pragma unroll
            for (int s = 0; s < 3; s++) {
                float v = b[row * RES + s * 32 + lane];
                c += __popc(__ballot_sync(0xffffffffu, v > 0.0f));
            }
            if (lane == 0) cnts[row] = c;
        }
    }
    __syncthreads();

    if (wid == 0) {  // exclusive prefix over 96 row counts
        int a0 = cnts[lane], a1 = cnts[lane + 32], a2 = cnts[lane + 64];
        int s0 = a0, s1 = a1, s2 = a2;
        #pragma unroll
        for (int d = 1; d < 32; d <<= 1) {
            int t0 = __shfl_up_sync(0xffffffffu, s0, d); if (lane >= d) s0 += t0;
            int t1 = __shfl_up_sync(0xffffffffu, s1, d); if (lane >= d) s1 += t1;
            int t2 = __shfl_up_sync(0xffffffffu, s2, d); if (lane >= d) s2 += t2;
        }
        s1 += __shfl_sync(0xffffffffu, s0, 31);
        s2 += __shfl_sync(0xffffffffu, s1, 31);
        offs[lane]      = s0 - a0;
        offs[lane + 32] = s1 - a1;
        offs[lane + 64] = s2 - a2;
        if (lane == 31) sK = s2;
    }
    __syncthreads();

    {   // scatter
        const int r0 = wid * 3;
        #pragma unroll
        for (int rr = 0; rr < 3; rr++) {
            const int row = r0 + rr;
            int p = offs[row];
            #pragma unroll
            for (int s = 0; s < 3; s++) {
                const int col = s * 32 + lane;
                float v = b[row * RES + col];
                unsigned m = __ballot_sync(0xffffffffu, v > 0.0f);
                if (v > 0.0f) {
                    int pos = p + __popc(m & ((1u << lane) - 1u));
                    entA[pos] = make_float4(-(float)row, -(float)row,
                                            -(float)col, -(float)col);
                    float* wp = reinterpret_cast<float*>(&entW[pos >> 1]);
                    const int o = (pos & 1) * 2;
                    wp[o]     = v;
                    wp[o + 1] = v;
                }
                p += __popc(m);
            }
        }
    }
    __syncthreads();

    // ---------------- window placement (R3-proven) ----------------
    const int pp  = blockIdx.x / 3;
    const int g   = blockIdx.x % 3;
    const int i0  = 2 * pp;

    const int a0i = abs(i0 - 48);
    const int a1i = abs(i0 + 1 - 48);
    const int dmin = a0i < a1i ? a0i : a1i;
    int s_ = 2208 - dmin * dmin; if (s_ < 0) s_ = 0;
    const int wmax = (int)sqrtf((float)s_) + 1;   // over-estimate: safe
    int J0 = 48 - wmax; if (J0 < 0) J0 = 0;

    const int j   = J0 + 32 * g + lane;           // may exceed 95 (guarded)
    const float fi0 = (float)i0;
    const float fj  = (float)j;

    const float dic0 = fi0 - CENTERF;
    const float dic1 = dic0 + 1.0f;
    const float djc  = fj - CENTERF;
    const float r2_0 = dic0 * dic0 + djc * djc;   // exact integer-valued
    const float r2_1 = dic1 * dic1 + djc * djc;
    const float z0 = CENTERF - sqrtf(r2_0) + EPSF;
    const float z1 = CENTERF - sqrtf(r2_1) + EPSF;
    const float c00 = fmaf(z0, z0, EPSF * EPSF);
    const float c01v = fmaf(z1, z1, EPSF * EPSF);

    const unsigned long long fi01 = pk2(fi0, fi0 + 1.0f);
    const unsigned long long fj2  = pk2(fj, fj);
    const unsigned long long c01  = pk2(c00, c01v);

    const bool allrim = __all_sync(0xffffffffu,
                                   (r2_0 >= RIM2) && (r2_1 >= RIM2));
    const int K  = sK;
    const int Kp = (K + 1) >> 1;                  // source pairs
    float f0 = 0.0f, f1 = 0.0f;

    // ---------------- Phase 2: paired-reciprocal f32x2 core ----------------
    if (!allrim) {
        unsigned long long acc = pk2(0.0f, 0.0f);
        const unsigned* baseA = reinterpret_cast<const unsigned*>(entA);
        const unsigned* baseW = reinterpret_cast<const unsigned*>(entW);
        (void)baseA; (void)baseW;

        #pragma unroll 4
        for (int p = wid; p < Kp; p += 32) {
            // load packed operands straight into register pairs
            unsigned long long A0i, A0j, A1i, A1j, W0, W1;
            asm("ld.shared.v2.u64 {%0, %1}, [%2];"
                : "=l"(A0i), "=l"(A0j)
                : "r"((unsigned)__cvta_generic_to_shared(&entA[2 * p])));
            asm("ld.shared.v2.u64 {%0, %1}, [%2];"
                : "=l"(A1i), "=l"(A1j)
                : "r"((unsigned)__cvta_generic_to_shared(&entA[2 * p + 1])));
            asm("ld.shared.v2.u64 {%0, %1}, [%2];"
                : "=l"(W0), "=l"(W1)
                : "r"((unsigned)__cvta_generic_to_shared(&entW[p])));

            unsigned long long di0, dj0, u0, a, di1, dj1, u1, bb;
            ADD2(di0, fi01, A0i);
            ADD2(dj0, fj2,  A0j);
            FMA2(u0, dj0, dj0, c01);
            FMA2(a,  di0, di0, u0);

            ADD2(di1, fi01, A1i);
            ADD2(dj1, fj2,  A1j);
            FMA2(u1, dj1, dj1, c01);
            FMA2(bb, di1, di1, u1);

            unsigned long long P, m, num;
            MUL2(P, a, bb);
            MUL2(m, W0, bb);
            FMA2(num, W1, a, m);

            float plo, phi, ilo, ihi;
            unpk2(P, plo, phi);
            asm("rcp.approx.ftz.f32 %0, %1;" : "=f"(ilo) : "f"(plo));
            asm("rcp.approx.ftz.f32 %0, %1;" : "=f"(ihi) : "f"(phi));
            unsigned long long inv = pk2(ilo, ihi);

            FMA2(acc, num, inv, acc);
        }
        unpk2(acc, f0, f1);
    }

    red[wid * 64 + lane]      = f0;
    red[wid * 64 + 32 + lane] = f1;
    __syncthreads();

    // ---------------- Phase 3: reduce + store ----------------
    if (tid < 64) {
        const int k = tid >> 5;                   // which of the two i-rows
        const int l = tid & 31;
        float s = 0.0f;
        #pragma unroll
        for (int w = 0; w < NWARPS; w++) s += red[w * 64 + k * 32 + l];

        const int jj = J0 + 32 * g + l;
        if (jj < RES) {
            const int ii  = i0 + k;
            const int di  = ii - 48, dj = jj - 48;
            const float bv = b[ii * RES + jj];
            out[ii * RES + jj] = (di * di + dj * dj >= 2209) ? bv : s;
        }
    }

    // Rim passthrough for uncovered columns j < J0 (provably rim).
    if (g == 0 && tid < RES) {
        if (tid < J0) {
            out[i0 * RES + tid]       = b[i0 * RES + tid];
            out[(i0 + 1) * RES + tid] = b[(i0 + 1) * RES + tid];
        }
    }
}

// ---------------------------------------------------------------------------
extern "C" void kernel_launch(void* const* d_in, const int* in_sizes, int n_in,
                              void* d_out, int out_size) {
    (void)in_sizes; (void)n_in; (void)out_size;
    const float* b   = (const float*)d_in[0];
    float*       out = (float*)d_out;

    const int smem_bytes = (CAPS + CAPP) * (int)sizeof(float4);  // 221184
    cudaFuncSetAttribute(fused_kernel,
                         cudaFuncAttributeMaxDynamicSharedMemorySize, smem_bytes);

    fused_kernel<<<144, 1024, smem_bytes>>>(b, out);
}